// round 1
// baseline (speedup 1.0000x reference)
#include <cuda_runtime.h>
#include <math.h>

#define B_  64
#define T_  2048
#define IN_ 128
#define H_  256
#define M_  (B_ * T_)   // 131072 rows for the projection GEMMs

// ---------------- scratch (static device allocations; no cudaMalloc) ----------------
__device__ float g_xp[(size_t)B_ * T_ * H_];   // 128 MB, reused for xp0 then xp1
__device__ float g_h1[(size_t)B_ * T_ * H_];   // layer-0 hidden states (also exchange medium)
__device__ float g_h2[(size_t)B_ * T_ * H_];   // layer-1 hidden states
__device__ int   g_flags[128];                 // [layer][bg*4+og] step-completion flags

// ---------------- packed fp32x2 helpers (sm_103a) ----------------
__device__ __forceinline__ void fma2(unsigned long long &d, unsigned long long a, unsigned long long b) {
    asm("fma.rn.f32x2 %0, %1, %2, %0;" : "+l"(d) : "l"(a), "l"(b));
}
__device__ __forceinline__ unsigned long long splat2(float x) {
    unsigned long long r; asm("mov.b64 %0, {%1, %1};" : "=l"(r) : "f"(x)); return r;
}
__device__ __forceinline__ float lo2(unsigned long long v) { return __uint_as_float((unsigned)(v & 0xffffffffULL)); }
__device__ __forceinline__ float hi2(unsigned long long v) { return __uint_as_float((unsigned)(v >> 32)); }

// =====================================================================================
// Phase A / C: C[m][n] = sum_k A[m][k] * W[n][k] + bias0[n] + bias1[n]
// A: [M,K] row-major, W: [N=256,K] row-major, C: [M,256].
// BM=128, BN=128, BK=16, 256 threads, 8x8 per thread via f32x2.
// =====================================================================================
__global__ __launch_bounds__(256, 2)
void gemm_bias_kernel(const float* __restrict__ A, const float* __restrict__ W,
                      const float* __restrict__ bias0, const float* __restrict__ bias1,
                      float* __restrict__ C, int K)
{
    __shared__ float a_sm[16][132];
    __shared__ float b_sm[16][132];

    const int tid = threadIdx.x;
    const int tx = tid & 15, ty = tid >> 4;
    const int mBase = blockIdx.x * 128;
    const int nBase = blockIdx.y * 128;

    unsigned long long acc[8][4];
#pragma unroll
    for (int i = 0; i < 8; i++)
#pragma unroll
        for (int j = 0; j < 4; j++) acc[i][j] = 0ULL;

    for (int kt = 0; kt < K; kt += 16) {
#pragma unroll
        for (int l = 0; l < 2; l++) {
            int idx = l * 256 + tid;
            int row = idx >> 2, kq = idx & 3;
            float4 v = *(const float4*)(A + (size_t)(mBase + row) * K + kt + kq * 4);
            a_sm[kq * 4 + 0][row] = v.x; a_sm[kq * 4 + 1][row] = v.y;
            a_sm[kq * 4 + 2][row] = v.z; a_sm[kq * 4 + 3][row] = v.w;
        }
#pragma unroll
        for (int l = 0; l < 2; l++) {
            int idx = l * 256 + tid;
            int row = idx >> 2, kq = idx & 3;
            float4 v = *(const float4*)(W + (size_t)(nBase + row) * K + kt + kq * 4);
            b_sm[kq * 4 + 0][row] = v.x; b_sm[kq * 4 + 1][row] = v.y;
            b_sm[kq * 4 + 2][row] = v.z; b_sm[kq * 4 + 3][row] = v.w;
        }
        __syncthreads();

#pragma unroll
        for (int kk = 0; kk < 16; kk++) {
            float4 a0 = *(const float4*)&a_sm[kk][ty * 8];
            float4 a1 = *(const float4*)&a_sm[kk][ty * 8 + 4];
            ulonglong2 b0 = *(const ulonglong2*)&b_sm[kk][tx * 8];
            ulonglong2 b1 = *(const ulonglong2*)&b_sm[kk][tx * 8 + 4];
            float av[8] = {a0.x, a0.y, a0.z, a0.w, a1.x, a1.y, a1.z, a1.w};
#pragma unroll
            for (int i = 0; i < 8; i++) {
                unsigned long long s = splat2(av[i]);
                fma2(acc[i][0], s, b0.x);
                fma2(acc[i][1], s, b0.y);
                fma2(acc[i][2], s, b1.x);
                fma2(acc[i][3], s, b1.y);
            }
        }
        __syncthreads();
    }

    const int n0 = nBase + tx * 8;
    float bj[8];
#pragma unroll
    for (int j = 0; j < 8; j++) bj[j] = bias0[n0 + j] + bias1[n0 + j];

#pragma unroll
    for (int i = 0; i < 8; i++) {
        int m = mBase + ty * 8 + i;
        float4 o0, o1;
        o0.x = lo2(acc[i][0]) + bj[0]; o0.y = hi2(acc[i][0]) + bj[1];
        o0.z = lo2(acc[i][1]) + bj[2]; o0.w = hi2(acc[i][1]) + bj[3];
        o1.x = lo2(acc[i][2]) + bj[4]; o1.y = hi2(acc[i][2]) + bj[5];
        o1.z = lo2(acc[i][3]) + bj[6]; o1.w = hi2(acc[i][3]) + bj[7];
        *(float4*)(C + (size_t)m * H_ + n0)     = o0;
        *(float4*)(C + (size_t)m * H_ + n0 + 4) = o1;
    }
}

// =====================================================================================
// Recurrent phase: persistent kernel, 64 CTAs = 16 batch-groups (Bc=4) x 4 out-splits (No=64).
// Each CTA holds its 64x256 fp32 slice of W_hh in padded SMEM, loops over all T steps.
// Per step: poll peer flags -> load full h[t-1] (4 rows) -> k-split matvec with f32x2 ->
// smem partial reduction -> tanh -> store h[t] chunk -> fence -> set flag.
// SMEM layout padded to 36-float k-chunks to avoid 128B-stride bank conflicts.
// =====================================================================================
#define REC_SMEM_FLOATS (64 * 288 + 4 * 288 + 8 * 264)
#define REC_SMEM_BYTES  (REC_SMEM_FLOATS * 4)

__global__ __launch_bounds__(256, 1)
void rnn_rec_kernel(const float* __restrict__ xp, const float* __restrict__ Whh,
                    float* __restrict__ hout, int* flags)
{
    extern __shared__ float sm[];
    float* W_sm = sm;                 // 64 rows * 288 (8 chunks of 36)
    float* h_sm = sm + 64 * 288;      // 4 rows  * 288
    float* p_sm = h_sm + 4 * 288;     // 8 kchunks * 264

    const int tid = threadIdx.x;
    const int bg = blockIdx.x & 15;   // batch group: rows bg*4 .. bg*4+3
    const int og = blockIdx.x >> 4;   // output split: cols og*64 .. og*64+63

    // Load W_hh rows [og*64, og*64+64) into padded smem
    for (int idx = tid; idx < 64 * 64; idx += 256) {
        int o = idx >> 6, c4 = idx & 63;
        float4 v = *(const float4*)(Whh + (size_t)(og * 64 + o) * H_ + c4 * 4);
        int col = c4 * 4, kcc = col >> 5, j = col & 31;
        *(float4*)(W_sm + o * 288 + kcc * 36 + j) = v;
    }
    __syncthreads();

    const int og2 = tid >> 3;  // output pair 0..31
    const int kc  = tid & 7;   // k chunk 0..7 (32 k each)
    const float* w0p = W_sm + (og2 * 2) * 288 + kc * 36;
    const float* w1p = w0p + 288;

    const int eb = tid >> 6;       // epilogue batch row 0..3
    const int eo = tid & 63;       // epilogue output 0..63
    const size_t ebase = ((size_t)(bg * 4 + eb) * T_) * H_ + og * 64 + eo;

    volatile int* myflags = (volatile int*)(flags + bg * 4);

    for (int t = 0; t < T_; ++t) {
        if (t > 0) {
            if (tid < 4) { while (myflags[tid] < t) { } }
        }
        __syncthreads();

        // prefetch xp value for the epilogue (long-latency, hidden under matvec)
        float xv = xp[ebase + (size_t)t * H_ - (size_t)0];  // xp[b][t][og*64+eo]
        xv = xp[(((size_t)(bg * 4 + eb) * T_) + t) * H_ + og * 64 + eo];

        // load h[t-1] (full 256 dims for our 4 batch rows) into padded smem
        {
            int b = tid >> 6, c4 = tid & 63;
            int col = c4 * 4, kcc = col >> 5, j = col & 31;
            float4 v = make_float4(0.f, 0.f, 0.f, 0.f);
            if (t > 0)
                v = *(const float4*)(hout + (((size_t)(bg * 4 + b) * T_) + (t - 1)) * H_ + c4 * 4);
            *(float4*)(h_sm + b * 288 + kcc * 36 + j) = v;
        }
        __syncthreads();

        // k-split matvec: 2 outputs x 4 batch rows, 32 k's, packed f32x2
        unsigned long long acc0[4] = {0, 0, 0, 0};
        unsigned long long acc1[4] = {0, 0, 0, 0};
#pragma unroll
        for (int g = 0; g < 8; ++g) {
            ulonglong2 w0 = *(const ulonglong2*)(w0p + g * 4);
            ulonglong2 w1 = *(const ulonglong2*)(w1p + g * 4);
#pragma unroll
            for (int b = 0; b < 4; ++b) {
                ulonglong2 hv = *(const ulonglong2*)(h_sm + b * 288 + kc * 36 + g * 4);
                fma2(acc0[b], hv.x, w0.x);
                fma2(acc0[b], hv.y, w0.y);
                fma2(acc1[b], hv.x, w1.x);
                fma2(acc1[b], hv.y, w1.y);
            }
        }

        // write partial sums (padded: stride 264 kills bank conflicts)
#pragma unroll
        for (int b = 0; b < 4; ++b) {
            p_sm[kc * 264 + og2 * 8 + b]     = lo2(acc0[b]) + hi2(acc0[b]);
            p_sm[kc * 264 + og2 * 8 + 4 + b] = lo2(acc1[b]) + hi2(acc1[b]);
        }
        __syncthreads();

        // epilogue: reduce 8 k-chunk partials, add xp, tanh, store h[t]
        float s = xv;
#pragma unroll
        for (int kcc = 0; kcc < 8; ++kcc)
            s += p_sm[kcc * 264 + (eo >> 1) * 8 + (eo & 1) * 4 + eb];
        float hval = tanhf(s);
        hout[(((size_t)(bg * 4 + eb) * T_) + t) * H_ + og * 64 + eo] = hval;

        __threadfence();
        __syncthreads();
        if (tid == 0) atomicExch(flags + bg * 4 + og, t + 1);
    }
}

// =====================================================================================
// Final FC: out[b] = dot(h2[b, T-1, :], W_fc[0,:]) + b_fc[0]
// =====================================================================================
__global__ void fc_kernel(const float* __restrict__ h2, const float* __restrict__ Wfc,
                          const float* __restrict__ bfc, float* __restrict__ out)
{
    __shared__ float red[8];
    int b = blockIdx.x, tid = threadIdx.x;
    float v = h2[(((size_t)b * T_) + (T_ - 1)) * H_ + tid] * Wfc[tid];
#pragma unroll
    for (int o = 16; o > 0; o >>= 1) v += __shfl_down_sync(0xffffffffu, v, o);
    if ((tid & 31) == 0) red[tid >> 5] = v;
    __syncthreads();
    if (tid < 8) {
        float s = red[tid];
#pragma unroll
        for (int o = 4; o > 0; o >>= 1) s += __shfl_down_sync(0xffu, s, o);
        if (tid == 0) out[b] = s + bfc[0];
    }
}

// =====================================================================================
extern "C" void kernel_launch(void* const* d_in, const int* in_sizes, int n_in,
                              void* d_out, int out_size)
{
    const float* x     = (const float*)d_in[0];
    const float* W_ih0 = (const float*)d_in[1];
    const float* W_hh0 = (const float*)d_in[2];
    const float* b_ih0 = (const float*)d_in[3];
    const float* b_hh0 = (const float*)d_in[4];
    const float* W_ih1 = (const float*)d_in[5];
    const float* W_hh1 = (const float*)d_in[6];
    const float* b_ih1 = (const float*)d_in[7];
    const float* b_hh1 = (const float*)d_in[8];
    const float* W_fc  = (const float*)d_in[9];
    const float* b_fc  = (const float*)d_in[10];
    float* out = (float*)d_out;

    float *xp, *h1, *h2; int* flags;
    cudaGetSymbolAddress((void**)&xp, g_xp);
    cudaGetSymbolAddress((void**)&h1, g_h1);
    cudaGetSymbolAddress((void**)&h2, g_h2);
    cudaGetSymbolAddress((void**)&flags, g_flags);

    cudaFuncSetAttribute(rnn_rec_kernel, cudaFuncAttributeMaxDynamicSharedMemorySize, REC_SMEM_BYTES);

    // reset step flags (captured as a memset node; re-runs on every replay)
    cudaMemsetAsync(flags, 0, 128 * sizeof(int), 0);

    dim3 ggemm(M_ / 128, H_ / 128);

    // Phase A: xp0 = x @ W_ih0^T + b_ih0 + b_hh0
    gemm_bias_kernel<<<ggemm, 256>>>(x, W_ih0, b_ih0, b_hh0, xp, IN_);
    // Phase B: layer-0 recurrence -> h1
    rnn_rec_kernel<<<64, 256, REC_SMEM_BYTES>>>(xp, W_hh0, h1, flags);
    // Phase C: xp1 = h1 @ W_ih1^T + b_ih1 + b_hh1 (overwrites xp scratch)
    gemm_bias_kernel<<<ggemm, 256>>>(h1, W_ih1, b_ih1, b_hh1, xp, H_);
    // Phase D: layer-1 recurrence -> h2
    rnn_rec_kernel<<<64, 256, REC_SMEM_BYTES>>>(xp, W_hh1, h2, flags + 64);
    // Phase E: final projection
    fc_kernel<<<B_, H_>>>(h2, W_fc, b_fc, out);
}

// round 2
// speedup vs baseline: 4.0687x; 4.0687x over previous
#include <cuda_runtime.h>
#include <math.h>

#define B_  64
#define T_  2048
#define IN_ 128
#define H_  256
#define M_  (B_ * T_)

// ---------------- scratch (static device allocations; no cudaMalloc) ----------------
__device__ float g_xp[(size_t)B_ * T_ * H_];   // reused for xp0 then xp1
__device__ float g_h1[(size_t)B_ * T_ * H_];   // layer-0 hidden states
__device__ float g_h2[(size_t)B_ * T_ * H_];   // layer-1 hidden states

// ---------------- packed fp32x2 helpers (sm_103a) ----------------
__device__ __forceinline__ void fma2(unsigned long long &d, unsigned long long a, unsigned long long b) {
    asm("fma.rn.f32x2 %0, %1, %2, %0;" : "+l"(d) : "l"(a), "l"(b));
}
__device__ __forceinline__ unsigned long long splat2(float x) {
    unsigned long long r; asm("mov.b64 %0, {%1, %1};" : "=l"(r) : "f"(x)); return r;
}
__device__ __forceinline__ float lo2(unsigned long long v) { return __uint_as_float((unsigned)(v & 0xffffffffULL)); }
__device__ __forceinline__ float hi2(unsigned long long v) { return __uint_as_float((unsigned)(v >> 32)); }

// ---------------- cluster / mbarrier helpers ----------------
__device__ __forceinline__ unsigned su32(const void* p) {
    return (unsigned)__cvta_generic_to_shared(p);
}
__device__ __forceinline__ unsigned cta_rank() {
    unsigned r; asm("mov.u32 %0, %%cluster_ctarank;" : "=r"(r)); return r;
}
__device__ __forceinline__ unsigned mapa_u32(unsigned addr, unsigned rank) {
    unsigned r; asm("mapa.shared::cluster.u32 %0, %1, %2;" : "=r"(r) : "r"(addr), "r"(rank));
    return r;
}
__device__ __forceinline__ void mbar_init(unsigned addr, unsigned cnt) {
    asm volatile("mbarrier.init.shared.b64 [%0], %1;" :: "r"(addr), "r"(cnt) : "memory");
}
__device__ __forceinline__ void mbar_expect_tx(unsigned addr, unsigned bytes) {
    asm volatile("mbarrier.arrive.expect_tx.shared.b64 _, [%0], %1;" :: "r"(addr), "r"(bytes) : "memory");
}
__device__ __forceinline__ void mbar_wait_cluster(unsigned addr, unsigned parity) {
    asm volatile(
        "{\n\t.reg .pred P;\n\t"
        "WL_%=:\n\t"
        "mbarrier.try_wait.parity.acquire.cluster.shared::cta.b64 P, [%0], %1, 0x989680;\n\t"
        "@P bra.uni WD_%=;\n\t"
        "bra.uni WL_%=;\n\t"
        "WD_%=:\n\t}"
        :: "r"(addr), "r"(parity) : "memory");
}
// remote smem store with transaction-count completion on the remote CTA's mbarrier
__device__ __forceinline__ void st_async_f32(unsigned remote_addr, float v, unsigned remote_mbar) {
    asm volatile(
        "st.async.shared::cluster.mbarrier::complete_tx::bytes.b32 [%0], %1, [%2];"
        :: "r"(remote_addr), "r"(__float_as_uint(v)), "r"(remote_mbar) : "memory");
}
__device__ __forceinline__ void cluster_sync_() {
    asm volatile("barrier.cluster.arrive.aligned;" ::: "memory");
    asm volatile("barrier.cluster.wait.aligned;" ::: "memory");
}

// =====================================================================================
// Phase A / C: C[m][n] = sum_k A[m][k] * W[n][k] + bias0[n] + bias1[n]
// =====================================================================================
__global__ __launch_bounds__(256, 2)
void gemm_bias_kernel(const float* __restrict__ A, const float* __restrict__ W,
                      const float* __restrict__ bias0, const float* __restrict__ bias1,
                      float* __restrict__ C, int K)
{
    __shared__ float a_sm[16][132];
    __shared__ float b_sm[16][132];

    const int tid = threadIdx.x;
    const int tx = tid & 15, ty = tid >> 4;
    const int mBase = blockIdx.x * 128;
    const int nBase = blockIdx.y * 128;

    unsigned long long acc[8][4];
#pragma unroll
    for (int i = 0; i < 8; i++)
#pragma unroll
        for (int j = 0; j < 4; j++) acc[i][j] = 0ULL;

    for (int kt = 0; kt < K; kt += 16) {
#pragma unroll
        for (int l = 0; l < 2; l++) {
            int idx = l * 256 + tid;
            int row = idx >> 2, kq = idx & 3;
            float4 v = *(const float4*)(A + (size_t)(mBase + row) * K + kt + kq * 4);
            a_sm[kq * 4 + 0][row] = v.x; a_sm[kq * 4 + 1][row] = v.y;
            a_sm[kq * 4 + 2][row] = v.z; a_sm[kq * 4 + 3][row] = v.w;
        }
#pragma unroll
        for (int l = 0; l < 2; l++) {
            int idx = l * 256 + tid;
            int row = idx >> 2, kq = idx & 3;
            float4 v = *(const float4*)(W + (size_t)(nBase + row) * K + kt + kq * 4);
            b_sm[kq * 4 + 0][row] = v.x; b_sm[kq * 4 + 1][row] = v.y;
            b_sm[kq * 4 + 2][row] = v.z; b_sm[kq * 4 + 3][row] = v.w;
        }
        __syncthreads();

#pragma unroll
        for (int kk = 0; kk < 16; kk++) {
            float4 a0 = *(const float4*)&a_sm[kk][ty * 8];
            float4 a1 = *(const float4*)&a_sm[kk][ty * 8 + 4];
            ulonglong2 b0 = *(const ulonglong2*)&b_sm[kk][tx * 8];
            ulonglong2 b1 = *(const ulonglong2*)&b_sm[kk][tx * 8 + 4];
            float av[8] = {a0.x, a0.y, a0.z, a0.w, a1.x, a1.y, a1.z, a1.w};
#pragma unroll
            for (int i = 0; i < 8; i++) {
                unsigned long long s = splat2(av[i]);
                fma2(acc[i][0], s, b0.x);
                fma2(acc[i][1], s, b0.y);
                fma2(acc[i][2], s, b1.x);
                fma2(acc[i][3], s, b1.y);
            }
        }
        __syncthreads();
    }

    const int n0 = nBase + tx * 8;
    float bj[8];
#pragma unroll
    for (int j = 0; j < 8; j++) bj[j] = bias0[n0 + j] + bias1[n0 + j];

#pragma unroll
    for (int i = 0; i < 8; i++) {
        int m = mBase + ty * 8 + i;
        float4 o0, o1;
        o0.x = lo2(acc[i][0]) + bj[0]; o0.y = hi2(acc[i][0]) + bj[1];
        o0.z = lo2(acc[i][1]) + bj[2]; o0.w = hi2(acc[i][1]) + bj[3];
        o1.x = lo2(acc[i][2]) + bj[4]; o1.y = hi2(acc[i][2]) + bj[5];
        o1.z = lo2(acc[i][3]) + bj[6]; o1.w = hi2(acc[i][3]) + bj[7];
        *(float4*)(C + (size_t)m * H_ + n0)     = o0;
        *(float4*)(C + (size_t)m * H_ + n0 + 4) = o1;
    }
}

// =====================================================================================
// Recurrence: 64 clusters of 2 CTAs (1 batch row per cluster), 256 threads/CTA.
// CTA rank r owns W_hh rows [r*128, r*128+128) held ENTIRELY IN REGISTERS
// (thread (o, kh) holds W[r*128+o][kh*128 .. kh*128+127] as 64 packed f32x2 regs).
// Per step: wait peer mbarrier -> matvec from SMEM h (broadcast LDS) -> smem pair
// reduction -> tanh -> write own h chunk locally + push to peer via st.async
// (mbarrier complete_tx). Double-buffered h, two mbarriers (phase p -> mbar[p&1]).
// =====================================================================================
__global__ void __cluster_dims__(2, 1, 1) __launch_bounds__(256, 1)
rnn_rec_cluster(const float* __restrict__ xp, const float* __restrict__ Whh,
                float* __restrict__ hout)
{
    __shared__ __align__(16) float h_sm[2][256];
    __shared__ __align__(16) float p_sm[256];
    __shared__ __align__(8)  unsigned long long mbar[2];

    const int tid = threadIdx.x;
    const unsigned rank = cta_rank();              // 0 or 1
    const unsigned peer = rank ^ 1u;
    const int b = blockIdx.x >> 1;                 // batch row
    const int w = tid >> 5, l = tid & 31;
    const int kh = w & 1;                          // k-half (0: k<128, 1: k>=128)
    const int o  = (w >> 1) * 32 + l;              // local output 0..127
    const int rbase = (int)rank * 128;

    // ---- load W slice into registers (64 packed f32x2 = 128 floats/thread) ----
    unsigned long long wq[64];
    {
        const ulonglong2* src = (const ulonglong2*)(Whh + (size_t)(rbase + o) * H_ + kh * 128);
#pragma unroll
        for (int j = 0; j < 32; ++j) { ulonglong2 v = src[j]; wq[2 * j] = v.x; wq[2 * j + 1] = v.y; }
    }

    // ---- init ----
    if (tid == 0) { mbar_init(su32(&mbar[0]), 1); mbar_init(su32(&mbar[1]), 1); }
    for (int i = tid; i < 512; i += 256) ((float*)h_sm)[i] = 0.f;   // h[-1] = 0
    __syncthreads();
    if (tid == 0) mbar_expect_tx(su32(&mbar[0]), 512);              // phase 0
    cluster_sync_();                                                 // peer mbars live

    const unsigned mbar_base   = su32(&mbar[0]);
    const unsigned peer_mbar0  = mapa_u32(mbar_base, peer);
    const unsigned peer_h0     = mapa_u32(su32(&h_sm[0][0]), peer);

    float xv = (tid < 128) ? __ldg(xp + ((size_t)b * T_) * H_ + rbase + tid) : 0.f;

    for (int t = 0; t < T_; ++t) {
        // prefetch xp for t+1 (latency hidden under wait + compute)
        float xvn = 0.f;
        if (tid < 128 && t + 1 < T_)
            xvn = __ldg(xp + ((size_t)b * T_ + t + 1) * H_ + rbase + tid);

        if (t > 0) {
            // wait phase t-1 (peer's h[t-1] chunk) on mbar[(t-1)&1]
            mbar_wait_cluster(mbar_base + ((unsigned)(t - 1) & 1u) * 8u,
                              ((unsigned)(t - 1) >> 1) & 1u);
            if (tid == 0) mbar_expect_tx(mbar_base + ((unsigned)t & 1u) * 8u, 512);
        }

        // ---- matvec: this thread's 128-k partial for output o ----
        const float* hb = &h_sm[t & 1][kh * 128];
        unsigned long long a0 = 0, a1 = 0;
#pragma unroll
        for (int kk = 0; kk < 32; ++kk) {
            ulonglong2 hv = *(const ulonglong2*)(hb + kk * 4);   // broadcast across warp
            fma2(a0, hv.x, wq[2 * kk]);
            fma2(a1, hv.y, wq[2 * kk + 1]);
        }
        p_sm[kh * 128 + o] = lo2(a0) + hi2(a0) + lo2(a1) + hi2(a1);
        __syncthreads();

        // ---- epilogue: combine k-halves, tanh, distribute h[t] ----
        if (tid < 128) {
            float s = xv + p_sm[tid] + p_sm[128 + tid];
            float h = tanhf(s);
            const int nb = (t + 1) & 1;
            h_sm[nb][rbase + tid] = h;                                   // own copy
            st_async_f32(peer_h0 + (unsigned)(nb * 256 + rbase + tid) * 4u,
                         h, peer_mbar0 + ((unsigned)t & 1u) * 8u);       // peer copy + tx
            hout[((size_t)b * T_ + t) * H_ + rbase + tid] = h;           // global
        }
        __syncthreads();
        xv = xvn;
    }

    // drain: ensure the final incoming st.async batch landed before any CTA exits
    mbar_wait_cluster(mbar_base + ((unsigned)(T_ - 1) & 1u) * 8u,
                      ((unsigned)(T_ - 1) >> 1) & 1u);
    cluster_sync_();
}

// =====================================================================================
// Final FC: out[b] = dot(h2[b, T-1, :], W_fc[0,:]) + b_fc[0]
// =====================================================================================
__global__ void fc_kernel(const float* __restrict__ h2, const float* __restrict__ Wfc,
                          const float* __restrict__ bfc, float* __restrict__ out)
{
    __shared__ float red[8];
    int b = blockIdx.x, tid = threadIdx.x;
    float v = h2[(((size_t)b * T_) + (T_ - 1)) * H_ + tid] * Wfc[tid];
#pragma unroll
    for (int o = 16; o > 0; o >>= 1) v += __shfl_down_sync(0xffffffffu, v, o);
    if ((tid & 31) == 0) red[tid >> 5] = v;
    __syncthreads();
    if (tid < 8) {
        float s = red[tid];
#pragma unroll
        for (int o = 4; o > 0; o >>= 1) s += __shfl_down_sync(0xffu, s, o);
        if (tid == 0) out[b] = s + bfc[0];
    }
}

// =====================================================================================
extern "C" void kernel_launch(void* const* d_in, const int* in_sizes, int n_in,
                              void* d_out, int out_size)
{
    const float* x     = (const float*)d_in[0];
    const float* W_ih0 = (const float*)d_in[1];
    const float* W_hh0 = (const float*)d_in[2];
    const float* b_ih0 = (const float*)d_in[3];
    const float* b_hh0 = (const float*)d_in[4];
    const float* W_ih1 = (const float*)d_in[5];
    const float* W_hh1 = (const float*)d_in[6];
    const float* b_ih1 = (const float*)d_in[7];
    const float* b_hh1 = (const float*)d_in[8];
    const float* W_fc  = (const float*)d_in[9];
    const float* b_fc  = (const float*)d_in[10];
    float* out = (float*)d_out;

    float *xp, *h1, *h2;
    cudaGetSymbolAddress((void**)&xp, g_xp);
    cudaGetSymbolAddress((void**)&h1, g_h1);
    cudaGetSymbolAddress((void**)&h2, g_h2);

    dim3 ggemm(M_ / 128, H_ / 128);

    // Phase A: xp0 = x @ W_ih0^T + b_ih0 + b_hh0
    gemm_bias_kernel<<<ggemm, 256>>>(x, W_ih0, b_ih0, b_hh0, xp, IN_);
    // Phase B: layer-0 recurrence -> h1   (64 clusters x 2 CTAs)
    rnn_rec_cluster<<<128, 256>>>(xp, W_hh0, h1);
    // Phase C: xp1 = h1 @ W_ih1^T + b_ih1 + b_hh1
    gemm_bias_kernel<<<ggemm, 256>>>(h1, W_ih1, b_ih1, b_hh1, xp, H_);
    // Phase D: layer-1 recurrence -> h2
    rnn_rec_cluster<<<128, 256>>>(xp, W_hh1, h2);
    // Phase E: final projection
    fc_kernel<<<B_, H_>>>(h2, W_fc, b_fc, out);
}